// round 12
// baseline (speedup 1.0000x reference)
#include <cuda_runtime.h>
#include <math.h>
#include <stdint.h>

typedef unsigned long long ull;

__device__ float g_FH[8 * 1024 * 256];   // [b][m][c] (flat reshape of conv out)
__device__ float g_Qt[8 * 64 * 4096];    // [b][d][n]
__device__ float g_Kt[8 * 64 * 1024];    // [b][d][m]

__device__ __forceinline__ void fma2(ull &d, ull a, ull b) {
    asm("fma.rn.f32x2 %0, %1, %2, %0;" : "+l"(d) : "l"(a), "l"(b));
}
__device__ __forceinline__ ull mul2(ull a, ull b) {
    ull r; asm("mul.rn.f32x2 %0, %1, %2;" : "=l"(r) : "l"(a), "l"(b)); return r;
}
__device__ __forceinline__ ull pk2(float x) {
    ull r; asm("mov.b64 %0, {%1, %1};" : "=l"(r) : "r"(__float_as_uint(x))); return r;
}
__device__ __forceinline__ float2 upk(ull v) {
    float2 f; asm("mov.b64 {%0, %1}, %2;" : "=f"(f.x), "=f"(f.y) : "l"(v)); return f;
}
__device__ __forceinline__ uint32_t cvta_s(const void* p) {
    return (uint32_t)__cvta_generic_to_shared(p);
}
__device__ __forceinline__ void cp16(uint32_t dst, const void* src) {
    asm volatile("cp.async.cg.shared.global [%0], [%1], 16;\n" :: "r"(dst), "l"(src) : "memory");
}
__device__ __forceinline__ void cp_commit() {
    asm volatile("cp.async.commit_group;\n" ::: "memory");
}
template<int N> __device__ __forceinline__ void cp_wait() {
    asm volatile("cp.async.wait_group %0;\n" :: "n"(N) : "memory");
}

// ======================= conv+BN+ReLU (proven) =============================
__global__ void __launch_bounds__(256) conv_k(
    const float* __restrict__ FHin, const float* __restrict__ Wc,
    const float* __restrict__ gam, const float* __restrict__ bet,
    const float* __restrict__ mu,  const float* __restrict__ var)
{
    __shared__ float Ws[64 * 64];
    __shared__ float Xs[64 * 128];
    const int t = threadIdx.x, tx = t & 31, ty = t >> 5;
    const int st = blockIdx.x, ot = blockIdx.y, b = blockIdx.z;
    const float* Xg = FHin + (size_t)b * 512 * 1024 + st * 128;
    const float* Wg = Wc + (size_t)ot * 64 * 512;

    ull acc[8][2];
    #pragma unroll
    for (int r = 0; r < 8; r++) { acc[r][0] = 0ull; acc[r][1] = 0ull; }

    for (int kc = 0; kc < 8; kc++) {
        __syncthreads();
        #pragma unroll
        for (int i = 0; i < 16; i++) {
            int id = i * 256 + t; int row = id >> 6, col = id & 63;
            Ws[row * 64 + col] = Wg[(size_t)row * 512 + kc * 64 + col];
        }
        #pragma unroll
        for (int i = 0; i < 8; i++) {
            int id = i * 256 + t; int row = id >> 5, c4 = id & 31;
            *(float4*)&Xs[row * 128 + c4 * 4] =
                *(const float4*)(Xg + (size_t)(kc * 64 + row) * 1024 + c4 * 4);
        }
        __syncthreads();
        #pragma unroll 8
        for (int k = 0; k < 64; k++) {
            ull x0 = *(const ull*)&Xs[k * 128 + tx * 4];
            ull x1 = *(const ull*)&Xs[k * 128 + tx * 4 + 2];
            #pragma unroll
            for (int r = 0; r < 8; r++) {
                ull wv = pk2(Ws[(ty * 8 + r) * 64 + k]);
                fma2(acc[r][0], wv, x0);
                fma2(acc[r][1], wv, x1);
            }
        }
    }
    #pragma unroll
    for (int r = 0; r < 8; r++) {
        int o = ot * 64 + ty * 8 + r;
        float inv = gam[o] * rsqrtf(var[o] + 1e-5f);
        float bs  = bet[o] - mu[o] * inv;
        float2 a = upk(acc[r][0]), c2 = upk(acc[r][1]);
        float4 v;
        v.x = fmaxf(fmaf(a.x,  inv, bs), 0.f);
        v.y = fmaxf(fmaf(a.y,  inv, bs), 0.f);
        v.z = fmaxf(fmaf(c2.x, inv, bs), 0.f);
        v.w = fmaxf(fmaf(c2.y, inv, bs), 0.f);
        *(float4*)&g_FH[((size_t)b * 256 + o) * 1024 + st * 128 + tx * 4] = v;
    }
}

// ==== fc GEMM, transposed store; destination resolved IN DEVICE CODE =======
template<bool TO_KT, int LOGW>
__global__ void __launch_bounds__(256) fcT_k(
    const float* __restrict__ Xin, const float* __restrict__ W,
    const float* __restrict__ bias)
{
    __shared__ float Xs[128 * 64];
    __shared__ float Ws[64 * 66];
    const int t = threadIdx.x, tx = t & 15, ty = t >> 4;
    const int n0 = blockIdx.x * 128;
    const int WW = 1 << LOGW;
    const float* X = TO_KT ? (const float*)g_FH : Xin;
    float* dst = TO_KT ? g_Kt : g_Qt;        // device-side symbol -> valid address

    ull acc[8][2];
    #pragma unroll
    for (int r = 0; r < 8; r++) { acc[r][0] = 0ull; acc[r][1] = 0ull; }

    for (int kc = 0; kc < 4; kc++) {
        __syncthreads();
        #pragma unroll
        for (int i = 0; i < 8; i++) {
            int id = i * 256 + t; int row = id >> 4, c4 = id & 15;
            *(float4*)&Xs[row * 64 + c4 * 4] =
                *(const float4*)(X + (size_t)(n0 + row) * 256 + kc * 64 + c4 * 4);
        }
        #pragma unroll
        for (int i = 0; i < 16; i++) {
            int id = i * 256 + t; int d = id >> 6, c = id & 63;
            Ws[c * 66 + d] = W[(size_t)d * 256 + kc * 64 + c];
        }
        __syncthreads();
        #pragma unroll 8
        for (int c = 0; c < 64; c++) {
            ull w0 = *(const ull*)&Ws[c * 66 + tx * 4];
            ull w1 = *(const ull*)&Ws[c * 66 + tx * 4 + 2];
            #pragma unroll
            for (int r = 0; r < 8; r++) {
                ull xv = pk2(Xs[(ty * 8 + r) * 64 + c]);
                fma2(acc[r][0], xv, w0);
                fma2(acc[r][1], xv, w1);
            }
        }
    }
    float4 bv = *(const float4*)(bias + tx * 4);
    #pragma unroll
    for (int r = 0; r < 8; r++) {
        int n = n0 + ty * 8 + r;
        int bb = n >> LOGW, nn = n & (WW - 1);
        float2 a = upk(acc[r][0]), c2 = upk(acc[r][1]);
        dst[((size_t)bb * 64 + tx * 4 + 0) * WW + nn] = a.x  + bv.x;
        dst[((size_t)bb * 64 + tx * 4 + 1) * WW + nn] = a.y  + bv.y;
        dst[((size_t)bb * 64 + tx * 4 + 2) * WW + nn] = c2.x + bv.z;
        dst[((size_t)bb * 64 + tx * 4 + 3) * WW + nn] = c2.y + bv.w;
    }
}

// ========================== fused attention ================================
// 256 thr / 8 warps, 64 Q-rows x 256 cols, 32 m-chunks of 32, 2 CTAs/SM.
#define Q_O 0
#define K_O 4096
#define F_O 8192
#define S_O 16384
#define T_O 18688
#define A_O 20864
#define I_O 20928
#define SMF 20992

__device__ __forceinline__ void issue_Kt(float* sm, const float* Ktg, int t, int c) {
    #pragma unroll
    for (int i = 0; i < 2; i++) {
        int id = i * 256 + t; int d = id >> 3, ch = id & 7;
        cp16(cvta_s(sm + K_O + (c & 1) * 2048 + d * 32 + ch * 4),
             Ktg + (size_t)d * 1024 + c * 32 + ch * 4);
    }
}
__device__ __forceinline__ void issue_FH(float* sm, const float* FHg, int t, int c) {
    #pragma unroll
    for (int i = 0; i < 8; i++) {
        int id = i * 256 + t; int m = id >> 6, ch = id & 63;
        cp16(cvta_s(sm + F_O + m * 256 + ch * 4),
             FHg + (size_t)(c * 32 + m) * 256 + ch * 4);
    }
}

__global__ void __launch_bounds__(256, 2) attn_k(
    const float* __restrict__ scp, float* __restrict__ out)
{
    extern __shared__ float sm[];
    const int b = blockIdx.y, nblk = blockIdx.x;
    const int t = threadIdx.x, w = t >> 5, l = t & 31;
    const int wr = w & 1, wc = w >> 1;
    const int rg = l >> 3, cg = l & 7;
    const int R0 = 32 * wr + 8 * rg, C0 = 64 * wc + 8 * cg;
    const int g2 = w >> 1, sl2 = w & 1;
    const int riS = l >> 2, cpS = l & 3;
    const int srow = 8 * w + (l >> 2), ms = l & 3;

    const float* Qtg = g_Qt + (size_t)b * 64 * 4096 + nblk * 64;
    const float* Ktg = g_Kt + (size_t)b * 64 * 1024;
    const float* FHg = g_FH + (size_t)b * 1024 * 256;

    #pragma unroll
    for (int i = 0; i < 4; i++) {
        int id = i * 256 + t; int d = id >> 4, ch = id & 15;
        cp16(cvta_s(sm + Q_O + d * 64 + ch * 4), Qtg + (size_t)d * 4096 + ch * 4);
    }
    issue_Kt(sm, Ktg, t, 0);
    cp_commit();

    ull o[8][4];
    #pragma unroll
    for (int i = 0; i < 8; i++)
        #pragma unroll
        for (int j = 0; j < 4; j++) o[i][j] = 0ull;
    float mrun = -INFINITY, lrun = 0.f;

    for (int c = 0; c < 32; c++) {
        issue_FH(sm, FHg, t, c);
        cp_commit();
        if (c < 31) { issue_Kt(sm, Ktg, t, c + 1); cp_commit(); cp_wait<2>(); }
        else        { cp_wait<1>(); }
        __syncthreads();

        // ---- S ----
        {
            const float* Kb = sm + K_O + (c & 1) * 2048 + 16 * sl2 + 4 * cpS;
            const float* qp = sm + Q_O + 16 * g2 + riS;
            ull s00 = 0ull, s01 = 0ull, s10 = 0ull, s11 = 0ull;
            #pragma unroll 8
            for (int d = 0; d < 64; d++) {
                ull kx = *(const ull*)(Kb + d * 32);
                ull ky = *(const ull*)(Kb + d * 32 + 2);
                ull q0 = pk2(qp[d * 64]);
                ull q1 = pk2(qp[d * 64 + 8]);
                fma2(s00, q0, kx); fma2(s01, q0, ky);
                fma2(s10, q1, kx); fma2(s11, q1, ky);
            }
            float* sp0 = sm + S_O + (16 * g2 + riS) * 36 + 16 * sl2 + 4 * cpS;
            *(ull*)sp0 = s00; *(ull*)(sp0 + 2) = s01;
            float* sp1 = sp0 + 8 * 36;
            *(ull*)sp1 = s10; *(ull*)(sp1 + 2) = s11;
        }
        __syncthreads();

        // ---- softmax (lane quad per row; 8 m per lane) ----
        {
            const float* sr = sm + S_O + srow * 36 + ms * 8;
            float4 a  = *(const float4*)sr;
            float4 b4 = *(const float4*)(sr + 4);
            float mt = fmaxf(fmaxf(fmaxf(a.x, a.y), fmaxf(a.z, a.w)),
                             fmaxf(fmaxf(b4.x, b4.y), fmaxf(b4.z, b4.w)));
            mt = fmaxf(mt, __shfl_xor_sync(0xffffffffu, mt, 1));
            mt = fmaxf(mt, __shfl_xor_sync(0xffffffffu, mt, 2));
            float mnew  = fmaxf(mrun, mt);
            float alpha = __expf(mrun - mnew);
            float e0 = __expf(a.x  - mnew), e1 = __expf(a.y  - mnew);
            float e2 = __expf(a.z  - mnew), e3 = __expf(a.w  - mnew);
            float e4 = __expf(b4.x - mnew), e5 = __expf(b4.y - mnew);
            float e6 = __expf(b4.z - mnew), e7 = __expf(b4.w - mnew);
            float ps = ((e0 + e1) + (e2 + e3)) + ((e4 + e5) + (e6 + e7));
            ps += __shfl_xor_sync(0xffffffffu, ps, 1);
            ps += __shfl_xor_sync(0xffffffffu, ps, 2);
            lrun = lrun * alpha + ps;
            mrun = mnew;
            if (ms == 0) sm[A_O + srow] = alpha;
            float* pp = sm + T_O + (ms * 8) * 68 + (srow ^ (8 * ms));
            pp[0 * 68] = e0; pp[1 * 68] = e1; pp[2 * 68] = e2; pp[3 * 68] = e3;
            pp[4 * 68] = e4; pp[5 * 68] = e5; pp[6 * 68] = e6; pp[7 * 68] = e7;
        }
        if (c < 31) cp_wait<1>(); else cp_wait<0>();
        __syncthreads();

        // ---- PV ----
        {
            #pragma unroll
            for (int i = 0; i < 8; i++) {
                ull a2 = pk2(sm[A_O + R0 + i]);
                o[i][0] = mul2(o[i][0], a2); o[i][1] = mul2(o[i][1], a2);
                o[i][2] = mul2(o[i][2], a2); o[i][3] = mul2(o[i][3], a2);
            }
            const float* Fb = sm + F_O + C0;
            const float* Pb = sm + T_O;
            #pragma unroll 2
            for (int m = 0; m < 32; m++) {
                int rsw = R0 ^ (8 * (m >> 3));
                float4 pa = *(const float4*)(Pb + m * 68 + rsw);
                float4 pb = *(const float4*)(Pb + m * 68 + rsw + 4);
                const float* fr = Fb + m * 256;
                ull f0 = *(const ull*)fr,       f1 = *(const ull*)(fr + 2);
                ull f2 = *(const ull*)(fr + 4), f3 = *(const ull*)(fr + 6);
                ull p;
                p = pk2(pa.x); fma2(o[0][0],p,f0); fma2(o[0][1],p,f1); fma2(o[0][2],p,f2); fma2(o[0][3],p,f3);
                p = pk2(pa.y); fma2(o[1][0],p,f0); fma2(o[1][1],p,f1); fma2(o[1][2],p,f2); fma2(o[1][3],p,f3);
                p = pk2(pa.z); fma2(o[2][0],p,f0); fma2(o[2][1],p,f1); fma2(o[2][2],p,f2); fma2(o[2][3],p,f3);
                p = pk2(pa.w); fma2(o[3][0],p,f0); fma2(o[3][1],p,f1); fma2(o[3][2],p,f2); fma2(o[3][3],p,f3);
                p = pk2(pb.x); fma2(o[4][0],p,f0); fma2(o[4][1],p,f1); fma2(o[4][2],p,f2); fma2(o[4][3],p,f3);
                p = pk2(pb.y); fma2(o[5][0],p,f0); fma2(o[5][1],p,f1); fma2(o[5][2],p,f2); fma2(o[5][3],p,f3);
                p = pk2(pb.z); fma2(o[6][0],p,f0); fma2(o[6][1],p,f1); fma2(o[6][2],p,f2); fma2(o[6][3],p,f3);
                p = pk2(pb.w); fma2(o[7][0],p,f0); fma2(o[7][1],p,f1); fma2(o[7][2],p,f2); fma2(o[7][3],p,f3);
            }
        }
        __syncthreads();
    }

    // ---- epilogue ----
    if (ms == 0) sm[I_O + srow] = scp[0] / lrun;
    __syncthreads();
    #pragma unroll
    for (int i = 0; i < 8; i++) {
        ull a2 = pk2(sm[I_O + R0 + i]);
        o[i][0] = mul2(o[i][0], a2); o[i][1] = mul2(o[i][1], a2);
        o[i][2] = mul2(o[i][2], a2); o[i][3] = mul2(o[i][3], a2);
    }
    float* stg = sm + F_O;                         // 32x257 staging (S region dead)
    float* outB = out + (size_t)b * 256 * 4096 + nblk * 64;
    for (int p = 0; p < 2; p++) {
        __syncthreads();
        if (wr == p) {
            #pragma unroll
            for (int i = 0; i < 8; i++)
                #pragma unroll
                for (int j = 0; j < 4; j++) {
                    float2 v = upk(o[i][j]);
                    stg[(8 * rg + i) * 257 + C0 + 2 * j]     = v.x;
                    stg[(8 * rg + i) * 257 + C0 + 2 * j + 1] = v.y;
                }
        }
        __syncthreads();
        #pragma unroll
        for (int k2 = 0; k2 < 8; k2++) {
            int idx = k2 * 256 + t;
            int ch = idx >> 3, ns = idx & 7;
            float4 v;
            v.x = stg[(ns * 4 + 0) * 257 + ch];
            v.y = stg[(ns * 4 + 1) * 257 + ch];
            v.z = stg[(ns * 4 + 2) * 257 + ch];
            v.w = stg[(ns * 4 + 3) * 257 + ch];
            *(float4*)(outB + (size_t)ch * 4096 + p * 32 + ns * 4) = v;
        }
    }
}

extern "C" void kernel_launch(void* const* d_in, const int* in_sizes, int n_in,
                              void* d_out, int out_size)
{
    conv_k<<<dim3(8, 4, 8), 256>>>((const float*)d_in[1], (const float*)d_in[2],
        (const float*)d_in[3], (const float*)d_in[4],
        (const float*)d_in[5], (const float*)d_in[6]);
    fcT_k<false, 12><<<256, 256>>>((const float*)d_in[0], (const float*)d_in[7],
                                   (const float*)d_in[8]);
    fcT_k<true,  10><<<64,  256>>>(nullptr, (const float*)d_in[9],
                                   (const float*)d_in[10]);
    cudaFuncSetAttribute(attn_k, cudaFuncAttributeMaxDynamicSharedMemorySize, SMF * 4);
    attn_k<<<dim3(64, 8), 256, SMF * 4>>>((const float*)d_in[11], (float*)d_out);
}

// round 14
// speedup vs baseline: 1.1157x; 1.1157x over previous
#include <cuda_runtime.h>
#include <math.h>
#include <stdint.h>
typedef unsigned long long ull;
typedef unsigned int u32;

__device__ float g_FH [8*1024*256];   // conv out [b][m][c]
__device__ float g_FHt[8*256*1024];   // [b][c][m]
__device__ float g_Q  [8*4096*64];    // [n][d]
__device__ float g_K  [8*1024*64];    // [m][d]

__device__ __forceinline__ void fma2(ull &d, ull a, ull b) {
    asm("fma.rn.f32x2 %0, %1, %2, %0;" : "+l"(d) : "l"(a), "l"(b));
}
__device__ __forceinline__ ull pk2(float x) {
    ull r; asm("mov.b64 %0, {%1, %1};" : "=l"(r) : "r"(__float_as_uint(x))); return r;
}
__device__ __forceinline__ float2 upk(ull v) {
    float2 f; asm("mov.b64 {%0, %1}, %2;" : "=f"(f.x), "=f"(f.y) : "l"(v)); return f;
}
__device__ __forceinline__ u32 cvta_s(const void* p) {
    return (u32)__cvta_generic_to_shared(p);
}
__device__ __forceinline__ void cp16(u32 dst, const void* src) {
    asm volatile("cp.async.cg.shared.global [%0], [%1], 16;\n" :: "r"(dst), "l"(src) : "memory");
}
__device__ __forceinline__ void cp_commit() {
    asm volatile("cp.async.commit_group;\n" ::: "memory");
}
template<int N> __device__ __forceinline__ void cp_wait() {
    asm volatile("cp.async.wait_group %0;\n" :: "n"(N) : "memory");
}
__device__ __forceinline__ u32 tf32c(float f) {
    u32 r; asm("cvt.rna.tf32.f32 %0, %1;" : "=r"(r) : "f"(f)); return r;
}
__device__ __forceinline__ void tsplit(float f, u32 &h, u32 &l) {
    h = tf32c(f); l = tf32c(f - __uint_as_float(h));
}
__device__ __forceinline__ void mma8(float* d, const u32* a, const u32* b) {
    asm volatile("mma.sync.aligned.m16n8k8.row.col.f32.tf32.tf32.f32 "
        "{%0,%1,%2,%3},{%4,%5,%6,%7},{%8,%9},{%0,%1,%2,%3};"
        : "+f"(d[0]), "+f"(d[1]), "+f"(d[2]), "+f"(d[3])
        : "r"(a[0]), "r"(a[1]), "r"(a[2]), "r"(a[3]), "r"(b[0]), "r"(b[1]));
}

// ======================= conv+BN+ReLU (proven) =============================
__global__ void __launch_bounds__(256) conv_k(
    const float* __restrict__ FHin, const float* __restrict__ Wc,
    const float* __restrict__ gam, const float* __restrict__ bet,
    const float* __restrict__ mu,  const float* __restrict__ var)
{
    __shared__ float Ws[64*64];
    __shared__ float Xs[64*128];
    const int t = threadIdx.x, tx = t & 31, ty = t >> 5;
    const int st = blockIdx.x, ot = blockIdx.y, b = blockIdx.z;
    const float* Xg = FHin + (size_t)b*512*1024 + st*128;
    const float* Wg = Wc + (size_t)ot*64*512;
    ull acc[8][2];
    #pragma unroll
    for (int r = 0; r < 8; r++) { acc[r][0] = 0ull; acc[r][1] = 0ull; }
    for (int kc = 0; kc < 8; kc++) {
        __syncthreads();
        #pragma unroll
        for (int i = 0; i < 16; i++) {
            int id = i*256 + t; int row = id >> 6, col = id & 63;
            Ws[row*64 + col] = Wg[(size_t)row*512 + kc*64 + col];
        }
        #pragma unroll
        for (int i = 0; i < 8; i++) {
            int id = i*256 + t; int row = id >> 5, c4 = id & 31;
            *(float4*)&Xs[row*128 + c4*4] =
                *(const float4*)(Xg + (size_t)(kc*64 + row)*1024 + c4*4);
        }
        __syncthreads();
        #pragma unroll 8
        for (int k = 0; k < 64; k++) {
            ull x0 = *(const ull*)&Xs[k*128 + tx*4];
            ull x1 = *(const ull*)&Xs[k*128 + tx*4 + 2];
            #pragma unroll
            for (int r = 0; r < 8; r++) {
                ull wv = pk2(Ws[(ty*8 + r)*64 + k]);
                fma2(acc[r][0], wv, x0);
                fma2(acc[r][1], wv, x1);
            }
        }
    }
    #pragma unroll
    for (int r = 0; r < 8; r++) {
        int o = ot*64 + ty*8 + r;
        float inv = gam[o] * rsqrtf(var[o] + 1e-5f);
        float bs  = bet[o] - mu[o]*inv;
        float2 a = upk(acc[r][0]), c2 = upk(acc[r][1]);
        float4 v;
        v.x = fmaxf(fmaf(a.x,  inv, bs), 0.f);
        v.y = fmaxf(fmaf(a.y,  inv, bs), 0.f);
        v.z = fmaxf(fmaf(c2.x, inv, bs), 0.f);
        v.w = fmaxf(fmaf(c2.y, inv, bs), 0.f);
        *(float4*)&g_FH[((size_t)b*256 + o)*1024 + st*128 + tx*4] = v;
    }
}

// ============== transpose g_FH [b][m][c] -> g_FHt [b][c][m] =================
__global__ void __launch_bounds__(256) transp_k()
{
    __shared__ float ts[64*65];
    const int t = threadIdx.x;
    const int i0 = blockIdx.x*64, j0 = blockIdx.y*64, b = blockIdx.z;
    const float* src = g_FH  + (size_t)b*1024*256;
    float*       dst = g_FHt + (size_t)b*256*1024;
    const int r = t >> 4, c4 = (t & 15)*4;
    #pragma unroll
    for (int k2 = 0; k2 < 4; k2++) {
        int il = r + k2*16;
        float4 v = *(const float4*)(src + (size_t)(i0+il)*256 + j0 + c4);
        ts[il*65 + c4+0] = v.x; ts[il*65 + c4+1] = v.y;
        ts[il*65 + c4+2] = v.z; ts[il*65 + c4+3] = v.w;
    }
    __syncthreads();
    #pragma unroll
    for (int k2 = 0; k2 < 4; k2++) {
        int jr = r + k2*16;
        float4 v;
        v.x = ts[(c4+0)*65 + jr]; v.y = ts[(c4+1)*65 + jr];
        v.z = ts[(c4+2)*65 + jr]; v.w = ts[(c4+3)*65 + jr];
        *(float4*)(dst + (size_t)(j0+jr)*1024 + i0 + c4) = v;
    }
}

// ======= fc GEMM (proven core), natural [n][64] store, dst device-side ======
template<bool TO_K>
__global__ void __launch_bounds__(256) fc_k(
    const float* __restrict__ Xin, const float* __restrict__ W,
    const float* __restrict__ bias)
{
    __shared__ float Xs[128*64];
    __shared__ float Ws[64*66];
    const int t = threadIdx.x, tx = t & 15, ty = t >> 4;
    const int n0 = blockIdx.x*128;
    const float* X = TO_K ? (const float*)g_FH : Xin;
    float* dst = TO_K ? g_K : g_Q;
    ull acc[8][2];
    #pragma unroll
    for (int r = 0; r < 8; r++) { acc[r][0] = 0ull; acc[r][1] = 0ull; }
    for (int kc = 0; kc < 4; kc++) {
        __syncthreads();
        #pragma unroll
        for (int i = 0; i < 8; i++) {
            int id = i*256 + t; int row = id >> 4, c4 = id & 15;
            *(float4*)&Xs[row*64 + c4*4] =
                *(const float4*)(X + (size_t)(n0+row)*256 + kc*64 + c4*4);
        }
        #pragma unroll
        for (int i = 0; i < 16; i++) {
            int id = i*256 + t; int d = id >> 6, c = id & 63;
            Ws[c*66 + d] = W[(size_t)d*256 + kc*64 + c];
        }
        __syncthreads();
        #pragma unroll 8
        for (int c = 0; c < 64; c++) {
            ull w0 = *(const ull*)&Ws[c*66 + tx*4];
            ull w1 = *(const ull*)&Ws[c*66 + tx*4 + 2];
            #pragma unroll
            for (int r = 0; r < 8; r++) {
                ull xv = pk2(Xs[(ty*8 + r)*64 + c]);
                fma2(acc[r][0], xv, w0);
                fma2(acc[r][1], xv, w1);
            }
        }
    }
    float4 bv = *(const float4*)(bias + tx*4);
    #pragma unroll
    for (int r = 0; r < 8; r++) {
        float2 a = upk(acc[r][0]), c2 = upk(acc[r][1]);
        float4 v = make_float4(a.x + bv.x, a.y + bv.y, c2.x + bv.z, c2.y + bv.w);
        *(float4*)&dst[(size_t)(n0 + ty*8 + r)*64 + tx*4] = v;
    }
}

// ============== attention via mma.sync tf32 (3xTF32 exact-ish) ==============
// 256 thr / 8 warps; block = 64 rows x 256 cols; 32 m-chunks of 32.
// S: warp (band=w&3, half=w>>2) -> rows 16band..+15, m 16half..+15.
// PV: warp (band, half) -> rows 16band..+15, cols 128half..+127; od persists.
#define QS_O 0          // Q  [64][68]
#define KS_O 4352       // K  2 x [32][68]
#define FS_O 8704       // FHt [256][36]
#define PH_O 17920      // P hi [64][36]
#define PL_O 20224      // P lo [64][36]
#define PS_O 22528      // partial sums [2][64]
#define LA_O 22656      // l accum [64]
#define SMF  22720

__global__ void __launch_bounds__(256, 2) attn_k(
    const float* __restrict__ scp, float* __restrict__ out)
{
    extern __shared__ float smf[];
    const u32 sb = cvta_s(smf);
    const int b = blockIdx.y, nblk = blockIdx.x;
    const int t = threadIdx.x, w = t >> 5, l = t & 31;
    const int gid = l >> 2, tid = l & 3;
    const int band = w & 3, half = w >> 2;

    const float* Qg = g_Q + ((size_t)b*4096 + nblk*64)*64;
    const float* Kg = g_K + (size_t)b*1024*64;
    const float* Fg = g_FHt + (size_t)b*256*1024;

    // prologue: group{Q, K0}, group{FHt0}
    #pragma unroll
    for (int i = 0; i < 4; i++) { int id = i*256 + t, r = id >> 4, q = id & 15;
        cp16(sb + (u32)(QS_O + r*68 + q*4)*4, Qg + (size_t)r*64 + q*4); }
    #pragma unroll
    for (int i = 0; i < 2; i++) { int id = i*256 + t, r = id >> 4, q = id & 15;
        cp16(sb + (u32)(KS_O + r*68 + q*4)*4, Kg + (size_t)r*64 + q*4); }
    cp_commit();
    #pragma unroll
    for (int i = 0; i < 8; i++) { int id = i*256 + t, cc = id >> 3, mm = id & 7;
        cp16(sb + (u32)(FS_O + cc*36 + mm*4)*4, Fg + (size_t)cc*1024 + mm*4); }
    cp_commit();

    if (t < 64) smf[LA_O + t] = 0.f;

    float od[16][4];
    #pragma unroll
    for (int i = 0; i < 16; i++) { od[i][0]=0.f; od[i][1]=0.f; od[i][2]=0.f; od[i][3]=0.f; }

    for (int c = 0; c < 32; c++) {
        cp_wait<1>();
        __syncthreads();

        // ---- S: 16x16 per warp, 3xTF32 ----
        float sd[2][4] = {{0,0,0,0},{0,0,0,0}};
        {
            const float* q0 = smf + QS_O + (16*band + gid)*68;
            const float* q1 = q0 + 8*68;
            const float* kb = smf + KS_O + (c & 1)*2176;
            #pragma unroll
            for (int kt = 0; kt < 8; kt++) {
                u32 ah[4], al[4];
                tsplit(q0[kt*8 + tid],     ah[0], al[0]);
                tsplit(q1[kt*8 + tid],     ah[1], al[1]);
                tsplit(q0[kt*8 + tid + 4], ah[2], al[2]);
                tsplit(q1[kt*8 + tid + 4], ah[3], al[3]);
                #pragma unroll
                for (int nt = 0; nt < 2; nt++) {
                    const float* kr = kb + (16*half + nt*8 + gid)*68 + kt*8;
                    u32 bh[2], bl[2];
                    tsplit(kr[tid],     bh[0], bl[0]);
                    tsplit(kr[tid + 4], bh[1], bl[1]);
                    mma8(sd[nt], ah, bh);
                    mma8(sd[nt], ah, bl);
                    mma8(sd[nt], al, bh);
                }
            }
        }
        if (c < 31) {
            const float* Kn = Kg + (size_t)(c + 1)*32*64;
            #pragma unroll
            for (int i = 0; i < 2; i++) { int id = i*256 + t, r = id >> 4, q = id & 15;
                cp16(sb + (u32)(KS_O + ((c + 1) & 1)*2176 + r*68 + q*4)*4,
                     Kn + (size_t)r*64 + q*4); }
            cp_commit();
        }

        // ---- softmax (naive; exact fp32 sums; P hi/lo pre-split to smem) ----
        {
            float e00 = __expf(sd[0][0]), e01 = __expf(sd[0][1]);
            float e02 = __expf(sd[0][2]), e03 = __expf(sd[0][3]);
            float e10 = __expf(sd[1][0]), e11 = __expf(sd[1][1]);
            float e12 = __expf(sd[1][2]), e13 = __expf(sd[1][3]);
            float l0 = (e00 + e01) + (e10 + e11);
            float l1 = (e02 + e03) + (e12 + e13);
            l0 += __shfl_xor_sync(~0u, l0, 1); l0 += __shfl_xor_sync(~0u, l0, 2);
            l1 += __shfl_xor_sync(~0u, l1, 1); l1 += __shfl_xor_sync(~0u, l1, 2);
            int r0 = 16*band + gid;
            if (tid == 0) {
                smf[PS_O + half*64 + r0]     = l0;
                smf[PS_O + half*64 + r0 + 8] = l1;
            }
            u32 h0, lo0, h1, lo1;
            int mb0 = 16*half + 2*tid;
            tsplit(e00, h0, lo0); tsplit(e01, h1, lo1);
            *(float2*)&smf[PH_O + r0*36 + mb0] = make_float2(__uint_as_float(h0), __uint_as_float(h1));
            *(float2*)&smf[PL_O + r0*36 + mb0] = make_float2(__uint_as_float(lo0), __uint_as_float(lo1));
            tsplit(e02, h0, lo0); tsplit(e03, h1, lo1);
            *(float2*)&smf[PH_O + (r0+8)*36 + mb0] = make_float2(__uint_as_float(h0), __uint_as_float(h1));
            *(float2*)&smf[PL_O + (r0+8)*36 + mb0] = make_float2(__uint_as_float(lo0), __uint_as_float(lo1));
            int mb1 = mb0 + 8;
            tsplit(e10, h0, lo0); tsplit(e11, h1, lo1);
            *(float2*)&smf[PH_O + r0*36 + mb1] = make_float2(__uint_as_float(h0), __uint_as_float(h1));
            *(float2*)&smf[PL_O + r0*36 + mb1] = make_float2(__uint_as_float(lo0), __uint_as_float(lo1));
            tsplit(e12, h0, lo0); tsplit(e13, h1, lo1);
            *(float2*)&smf[PH_O + (r0+8)*36 + mb1] = make_float2(__uint_as_float(h0), __uint_as_float(h1));
            *(float2*)&smf[PL_O + (r0+8)*36 + mb1] = make_float2(__uint_as_float(lo0), __uint_as_float(lo1));
        }
        if (c < 31) cp_wait<1>(); else cp_wait<0>();
        __syncthreads();
        if (t < 64) smf[LA_O + t] += smf[PS_O + t] + smf[PS_O + 64 + t];

        // ---- PV: 16x128 per warp, od += P . FHt^T (3xTF32) ----
        {
            u32 ph[4][4], pl[4][4];
            const float* Ph0 = smf + PH_O + (16*band + gid)*36;
            const float* Ph1 = Ph0 + 8*36;
            const float* Pl0 = smf + PL_O + (16*band + gid)*36;
            const float* Pl1 = Pl0 + 8*36;
            #pragma unroll
            for (int kt = 0; kt < 4; kt++) {
                ph[kt][0] = __float_as_uint(Ph0[kt*8 + tid]);
                ph[kt][1] = __float_as_uint(Ph1[kt*8 + tid]);
                ph[kt][2] = __float_as_uint(Ph0[kt*8 + tid + 4]);
                ph[kt][3] = __float_as_uint(Ph1[kt*8 + tid + 4]);
                pl[kt][0] = __float_as_uint(Pl0[kt*8 + tid]);
                pl[kt][1] = __float_as_uint(Pl1[kt*8 + tid]);
                pl[kt][2] = __float_as_uint(Pl0[kt*8 + tid + 4]);
                pl[kt][3] = __float_as_uint(Pl1[kt*8 + tid + 4]);
            }
            #pragma unroll
            for (int nt = 0; nt < 16; nt++) {
                const float* Fb = smf + FS_O + (128*half + nt*8 + gid)*36;
                #pragma unroll
                for (int kt = 0; kt < 4; kt++) {
                    u32 bh[2], bl[2];
                    tsplit(Fb[kt*8 + tid],     bh[0], bl[0]);
                    tsplit(Fb[kt*8 + tid + 4], bh[1], bl[1]);
                    mma8(od[nt], ph[kt], bh);
                    mma8(od[nt], ph[kt], bl);
                    mma8(od[nt], pl[kt], bh);
                }
            }
        }
        __syncthreads();
        if (c < 31) {
            const float* Fn = Fg + (size_t)(c + 1)*32;
            #pragma unroll
            for (int i = 0; i < 8; i++) { int id = i*256 + t, cc = id >> 3, mm = id & 7;
                cp16(sb + (u32)(FS_O + cc*36 + mm*4)*4, Fn + (size_t)cc*1024 + mm*4); }
            cp_commit();
        }
    }

    // ---- epilogue: scale by scp/l, store out[b][ch][n] ----
    float sc = scp[0];
    int r0 = 16*band + gid;
    float inv0 = sc / smf[LA_O + r0];
    float inv1 = sc / smf[LA_O + r0 + 8];
    float* outB = out + (size_t)b*256*4096 + nblk*64;
    #pragma unroll
    for (int nt = 0; nt < 16; nt++) {
        int ch = 128*half + nt*8 + 2*tid;
        float* p0 = outB + (size_t)ch*4096;
        p0[r0]          = od[nt][0]*inv0;
        p0[4096 + r0]   = od[nt][1]*inv0;
        p0[r0 + 8]      = od[nt][2]*inv1;
        p0[4096 + r0+8] = od[nt][3]*inv1;
    }
}

extern "C" void kernel_launch(void* const* d_in, const int* in_sizes, int n_in,
                              void* d_out, int out_size)
{
    conv_k<<<dim3(8, 4, 8), 256>>>((const float*)d_in[1], (const float*)d_in[2],
        (const float*)d_in[3], (const float*)d_in[4],
        (const float*)d_in[5], (const float*)d_in[6]);
    transp_k<<<dim3(16, 4, 8), 256>>>();
    fc_k<false><<<256, 256>>>((const float*)d_in[0], (const float*)d_in[7],
                              (const float*)d_in[8]);
    fc_k<true ><<<64,  256>>>(nullptr, (const float*)d_in[9],
                              (const float*)d_in[10]);
    cudaFuncSetAttribute(attn_k, cudaFuncAttributeMaxDynamicSharedMemorySize, SMF*4);
    attn_k<<<dim3(64, 8), 256, SMF*4>>>((const float*)d_in[11], (float*)d_out);
}

// round 15
// speedup vs baseline: 1.1420x; 1.0236x over previous
#include <cuda_runtime.h>
#include <math.h>
#include <stdint.h>
typedef unsigned long long ull;
typedef unsigned int u32;

__device__ float g_FH  [8*1024*256];  // conv out [b][m][c]
__device__ float g_Ft_hi[8*256*1024]; // FHt hi [b][c][m]
__device__ float g_Ft_lo[8*256*1024];
__device__ float g_Q   [8*4096*64];
__device__ float g_K_hi[8*1024*64];
__device__ float g_K_lo[8*1024*64];

__device__ __forceinline__ void fma2(ull &d, ull a, ull b) {
    asm("fma.rn.f32x2 %0, %1, %2, %0;" : "+l"(d) : "l"(a), "l"(b));
}
__device__ __forceinline__ ull pk2(float x) {
    ull r; asm("mov.b64 %0, {%1, %1};" : "=l"(r) : "r"(__float_as_uint(x))); return r;
}
__device__ __forceinline__ float2 upk(ull v) {
    float2 f; asm("mov.b64 {%0, %1}, %2;" : "=f"(f.x), "=f"(f.y) : "l"(v)); return f;
}
__device__ __forceinline__ u32 cvta_s(const void* p) {
    return (u32)__cvta_generic_to_shared(p);
}
__device__ __forceinline__ void cp16(u32 dst, const void* src) {
    asm volatile("cp.async.cg.shared.global [%0], [%1], 16;\n" :: "r"(dst), "l"(src) : "memory");
}
__device__ __forceinline__ void cp_commit() {
    asm volatile("cp.async.commit_group;\n" ::: "memory");
}
template<int N> __device__ __forceinline__ void cp_wait() {
    asm volatile("cp.async.wait_group %0;\n" :: "n"(N) : "memory");
}
__device__ __forceinline__ u32 tf32c(float f) {
    u32 r; asm("cvt.rna.tf32.f32 %0, %1;" : "=r"(r) : "f"(f)); return r;
}
__device__ __forceinline__ void tsplit(float f, u32 &h, u32 &l) {
    h = tf32c(f); l = tf32c(f - __uint_as_float(h));
}
__device__ __forceinline__ void mma8(float* d, const u32* a, const u32* b) {
    asm volatile("mma.sync.aligned.m16n8k8.row.col.f32.tf32.tf32.f32 "
        "{%0,%1,%2,%3},{%4,%5,%6,%7},{%8,%9},{%0,%1,%2,%3};"
        : "+f"(d[0]), "+f"(d[1]), "+f"(d[2]), "+f"(d[3])
        : "r"(a[0]), "r"(a[1]), "r"(a[2]), "r"(a[3]), "r"(b[0]), "r"(b[1]));
}
#define FB(x) __float_as_uint(x)

// ======================= conv+BN+ReLU (proven) =============================
__global__ void __launch_bounds__(256) conv_k(
    const float* __restrict__ FHin, const float* __restrict__ Wc,
    const float* __restrict__ gam, const float* __restrict__ bet,
    const float* __restrict__ mu,  const float* __restrict__ var)
{
    __shared__ float Ws[64*64];
    __shared__ float Xs[64*128];
    const int t = threadIdx.x, tx = t & 31, ty = t >> 5;
    const int st = blockIdx.x, ot = blockIdx.y, b = blockIdx.z;
    const float* Xg = FHin + (size_t)b*512*1024 + st*128;
    const float* Wg = Wc + (size_t)ot*64*512;
    ull acc[8][2];
    #pragma unroll
    for (int r = 0; r < 8; r++) { acc[r][0] = 0ull; acc[r][1] = 0ull; }
    for (int kc = 0; kc < 8; kc++) {
        __syncthreads();
        #pragma unroll
        for (int i = 0; i < 16; i++) {
            int id = i*256 + t; int row = id >> 6, col = id & 63;
            Ws[row*64 + col] = Wg[(size_t)row*512 + kc*64 + col];
        }
        #pragma unroll
        for (int i = 0; i < 8; i++) {
            int id = i*256 + t; int row = id >> 5, c4 = id & 31;
            *(float4*)&Xs[row*128 + c4*4] =
                *(const float4*)(Xg + (size_t)(kc*64 + row)*1024 + c4*4);
        }
        __syncthreads();
        #pragma unroll 8
        for (int k = 0; k < 64; k++) {
            ull x0 = *(const ull*)&Xs[k*128 + tx*4];
            ull x1 = *(const ull*)&Xs[k*128 + tx*4 + 2];
            #pragma unroll
            for (int r = 0; r < 8; r++) {
                ull wv = pk2(Ws[(ty*8 + r)*64 + k]);
                fma2(acc[r][0], wv, x0);
                fma2(acc[r][1], wv, x1);
            }
        }
    }
    #pragma unroll
    for (int r = 0; r < 8; r++) {
        int o = ot*64 + ty*8 + r;
        float inv = gam[o] * rsqrtf(var[o] + 1e-5f);
        float bs  = bet[o] - mu[o]*inv;
        float2 a = upk(acc[r][0]), c2 = upk(acc[r][1]);
        float4 v;
        v.x = fmaxf(fmaf(a.x,  inv, bs), 0.f);
        v.y = fmaxf(fmaf(a.y,  inv, bs), 0.f);
        v.z = fmaxf(fmaf(c2.x, inv, bs), 0.f);
        v.w = fmaxf(fmaf(c2.y, inv, bs), 0.f);
        *(float4*)&g_FH[((size_t)b*256 + o)*1024 + st*128 + tx*4] = v;
    }
}

// ====== transpose + tf32-split: g_FH [b][m][c] -> g_Ft_hi/lo [b][c][m] =====
__global__ void __launch_bounds__(256) transp_k()
{
    __shared__ float ts[64*65];
    const int t = threadIdx.x;
    const int i0 = blockIdx.x*64, j0 = blockIdx.y*64, b = blockIdx.z;
    const float* src = g_FH + (size_t)b*1024*256;
    float* dh = g_Ft_hi + (size_t)b*256*1024;
    float* dl = g_Ft_lo + (size_t)b*256*1024;
    const int r = t >> 4, c4 = (t & 15)*4;
    #pragma unroll
    for (int k2 = 0; k2 < 4; k2++) {
        int il = r + k2*16;
        float4 v = *(const float4*)(src + (size_t)(i0+il)*256 + j0 + c4);
        ts[il*65 + c4+0] = v.x; ts[il*65 + c4+1] = v.y;
        ts[il*65 + c4+2] = v.z; ts[il*65 + c4+3] = v.w;
    }
    __syncthreads();
    #pragma unroll
    for (int k2 = 0; k2 < 4; k2++) {
        int jr = r + k2*16;
        float4 v;
        v.x = ts[(c4+0)*65 + jr]; v.y = ts[(c4+1)*65 + jr];
        v.z = ts[(c4+2)*65 + jr]; v.w = ts[(c4+3)*65 + jr];
        float4 vh, vl; u32 h, lo;
        tsplit(v.x, h, lo); vh.x = __uint_as_float(h); vl.x = __uint_as_float(lo);
        tsplit(v.y, h, lo); vh.y = __uint_as_float(h); vl.y = __uint_as_float(lo);
        tsplit(v.z, h, lo); vh.z = __uint_as_float(h); vl.z = __uint_as_float(lo);
        tsplit(v.w, h, lo); vh.w = __uint_as_float(h); vl.w = __uint_as_float(lo);
        *(float4*)(dh + (size_t)(j0+jr)*1024 + i0 + c4) = vh;
        *(float4*)(dl + (size_t)(j0+jr)*1024 + i0 + c4) = vl;
    }
}

// ====== fc GEMM (proven core); Q raw, K split hi/lo =========================
template<bool TO_K>
__global__ void __launch_bounds__(256) fc_k(
    const float* __restrict__ Xin, const float* __restrict__ W,
    const float* __restrict__ bias)
{
    __shared__ float Xs[128*64];
    __shared__ float Ws[64*66];
    const int t = threadIdx.x, tx = t & 15, ty = t >> 4;
    const int n0 = blockIdx.x*128;
    const float* X = TO_K ? (const float*)g_FH : Xin;
    ull acc[8][2];
    #pragma unroll
    for (int r = 0; r < 8; r++) { acc[r][0] = 0ull; acc[r][1] = 0ull; }
    for (int kc = 0; kc < 4; kc++) {
        __syncthreads();
        #pragma unroll
        for (int i = 0; i < 8; i++) {
            int id = i*256 + t; int row = id >> 4, c4 = id & 15;
            *(float4*)&Xs[row*64 + c4*4] =
                *(const float4*)(X + (size_t)(n0+row)*256 + kc*64 + c4*4);
        }
        #pragma unroll
        for (int i = 0; i < 16; i++) {
            int id = i*256 + t; int d = id >> 6, c = id & 63;
            Ws[c*66 + d] = W[(size_t)d*256 + kc*64 + c];
        }
        __syncthreads();
        #pragma unroll 8
        for (int c = 0; c < 64; c++) {
            ull w0 = *(const ull*)&Ws[c*66 + tx*4];
            ull w1 = *(const ull*)&Ws[c*66 + tx*4 + 2];
            #pragma unroll
            for (int r = 0; r < 8; r++) {
                ull xv = pk2(Xs[(ty*8 + r)*64 + c]);
                fma2(acc[r][0], xv, w0);
                fma2(acc[r][1], xv, w1);
            }
        }
    }
    float4 bv = *(const float4*)(bias + tx*4);
    #pragma unroll
    for (int r = 0; r < 8; r++) {
        float2 a = upk(acc[r][0]), c2 = upk(acc[r][1]);
        float4 v = make_float4(a.x + bv.x, a.y + bv.y, c2.x + bv.z, c2.y + bv.w);
        size_t idx = (size_t)(n0 + ty*8 + r)*64 + tx*4;
        if (!TO_K) {
            *(float4*)&g_Q[idx] = v;
        } else {
            float4 vh, vl; u32 h, lo;
            tsplit(v.x, h, lo); vh.x = __uint_as_float(h); vl.x = __uint_as_float(lo);
            tsplit(v.y, h, lo); vh.y = __uint_as_float(h); vl.y = __uint_as_float(lo);
            tsplit(v.z, h, lo); vh.z = __uint_as_float(h); vl.z = __uint_as_float(lo);
            tsplit(v.w, h, lo); vh.w = __uint_as_float(h); vl.w = __uint_as_float(lo);
            *(float4*)&g_K_hi[idx] = vh;
            *(float4*)&g_K_lo[idx] = vl;
        }
    }
}

// ============== attention: mma.sync tf32, all operands pre-split ============
// 256 thr / 8 warps; 64 rows x 256 cols per block; 64 m-chunks of 16.
// S: warp (band=w&3, half=w>>2) -> rows 16band..+15, m 8half..+7 (1 tile).
// PV: warp (band, half) -> rows 16band..+15, cols 128half..+127 (16 tiles).
#define QH_O 0        // [64][68]
#define QL_O 4352
#define KH_O 8704     // 2 x [16][68]
#define KL_O 10880
#define FH_O 13056    // [256][20]
#define FL_O 18176
#define PH_O 23296    // [64][20]
#define PL_O 24576
#define PS_O 25856    // [2][64]
#define LA_O 25984    // [64]
#define SMF  26048

__global__ void __launch_bounds__(256, 2) attn_k(
    const float* __restrict__ scp, float* __restrict__ out)
{
    extern __shared__ float smf[];
    const u32 sb = cvta_s(smf);
    const int b = blockIdx.y, nblk = blockIdx.x;
    const int t = threadIdx.x, w = t >> 5, l = t & 31;
    const int gid = l >> 2, tid = l & 3;
    const int band = w & 3, half = w >> 2;
    const int r0 = 16*band + gid;

    const float* Qg  = g_Q    + ((size_t)b*4096 + nblk*64)*64;
    const float* Khg = g_K_hi + (size_t)b*1024*64;
    const float* Klg = g_K_lo + (size_t)b*1024*64;
    const float* Fhg = g_Ft_hi + (size_t)b*256*1024;
    const float* Flg = g_Ft_lo + (size_t)b*256*1024;

    // prologue: G1{Q raw, K0 hi/lo}, G2{F0 hi/lo}
    #pragma unroll
    for (int i = 0; i < 4; i++) { int id = i*256 + t, r = id >> 4, q = id & 15;
        cp16(sb + (u32)(QH_O + r*68 + q*4)*4, Qg + (size_t)r*64 + q*4); }
    { int r = t >> 4, q = t & 15;
      cp16(sb + (u32)(KH_O + r*68 + q*4)*4, Khg + (size_t)r*64 + q*4);
      cp16(sb + (u32)(KL_O + r*68 + q*4)*4, Klg + (size_t)r*64 + q*4); }
    cp_commit();
    #pragma unroll
    for (int i = 0; i < 4; i++) { int id = i*256 + t, cc = id >> 2, mm = id & 3;
        cp16(sb + (u32)(FH_O + cc*20 + mm*4)*4, Fhg + (size_t)cc*1024 + mm*4);
        cp16(sb + (u32)(FL_O + cc*20 + mm*4)*4, Flg + (size_t)cc*1024 + mm*4); }
    cp_commit();
    cp_wait<1>();
    __syncthreads();
    // split Q in place: QH -> hi, QL -> lo
    #pragma unroll
    for (int i = 0; i < 16; i++) {
        int id = i*256 + t, r = id >> 6, col = id & 63;
        float f = smf[QH_O + r*68 + col];
        u32 h, lo; tsplit(f, h, lo);
        smf[QH_O + r*68 + col] = __uint_as_float(h);
        smf[QL_O + r*68 + col] = __uint_as_float(lo);
    }
    if (t < 64) smf[LA_O + t] = 0.f;
    __syncthreads();

    float od[16][4];
    #pragma unroll
    for (int i = 0; i < 16; i++) { od[i][0]=0.f; od[i][1]=0.f; od[i][2]=0.f; od[i][3]=0.f; }

    for (int c = 0; c < 64; c++) {
        cp_wait<1>();
        __syncthreads();

        // ---- S: one 16x8 tile per warp ----
        float sd[4] = {0.f, 0.f, 0.f, 0.f};
        {
            const float* qh  = smf + QH_O + r0*68;
            const float* ql  = smf + QL_O + r0*68;
            const float* kh  = smf + KH_O + (c & 1)*1088 + (8*half + gid)*68;
            const float* kl  = smf + KL_O + (c & 1)*1088 + (8*half + gid)*68;
            #pragma unroll
            for (int kt = 0; kt < 8; kt++) {
                u32 ah[4], al[4], bh[2], bl[2];
                ah[0] = FB(qh[kt*8+tid]);       ah[1] = FB(qh[8*68 + kt*8+tid]);
                ah[2] = FB(qh[kt*8+tid+4]);     ah[3] = FB(qh[8*68 + kt*8+tid+4]);
                al[0] = FB(ql[kt*8+tid]);       al[1] = FB(ql[8*68 + kt*8+tid]);
                al[2] = FB(ql[kt*8+tid+4]);     al[3] = FB(ql[8*68 + kt*8+tid+4]);
                bh[0] = FB(kh[kt*8+tid]);       bh[1] = FB(kh[kt*8+tid+4]);
                bl[0] = FB(kl[kt*8+tid]);       bl[1] = FB(kl[kt*8+tid+4]);
                mma8(sd, ah, bh);
                mma8(sd, ah, bl);
                mma8(sd, al, bh);
            }
        }
        if (c < 63) {   // prefetch K(c+1) hi/lo
            const float* Khn = Khg + (size_t)(c+1)*16*64;
            const float* Kln = Klg + (size_t)(c+1)*16*64;
            int r = t >> 4, q = t & 15;
            u32 kb = (u32)(KH_O + ((c+1) & 1)*1088 + r*68 + q*4)*4;
            u32 lb = (u32)(KL_O + ((c+1) & 1)*1088 + r*68 + q*4)*4;
            cp16(sb + kb, Khn + (size_t)r*64 + q*4);
            cp16(sb + lb, Kln + (size_t)r*64 + q*4);
            cp_commit();
        }

        // ---- softmax (naive; safe since |S| <~ 45) ----
        {
            float e0 = __expf(sd[0]), e1 = __expf(sd[1]);
            float e2 = __expf(sd[2]), e3 = __expf(sd[3]);
            float l0 = e0 + e1, l1 = e2 + e3;
            l0 += __shfl_xor_sync(~0u, l0, 1); l0 += __shfl_xor_sync(~0u, l0, 2);
            l1 += __shfl_xor_sync(~0u, l1, 1); l1 += __shfl_xor_sync(~0u, l1, 2);
            if (tid == 0) {
                smf[PS_O + half*64 + r0]     = l0;
                smf[PS_O + half*64 + r0 + 8] = l1;
            }
            int mc = 8*half + 2*tid;
            u32 h0, q0, h1, q1;
            tsplit(e0, h0, q0); tsplit(e1, h1, q1);
            *(float2*)&smf[PH_O + r0*20 + mc] = make_float2(__uint_as_float(h0), __uint_as_float(h1));
            *(float2*)&smf[PL_O + r0*20 + mc] = make_float2(__uint_as_float(q0), __uint_as_float(q1));
            tsplit(e2, h0, q0); tsplit(e3, h1, q1);
            *(float2*)&smf[PH_O + (r0+8)*20 + mc] = make_float2(__uint_as_float(h0), __uint_as_float(h1));
            *(float2*)&smf[PL_O + (r0+8)*20 + mc] = make_float2(__uint_as_float(q0), __uint_as_float(q1));
        }
        if (c < 63) cp_wait<1>(); else cp_wait<0>();
        __syncthreads();
        if (t < 64) smf[LA_O + t] += smf[PS_O + t] + smf[PS_O + 64 + t];

        // ---- PV: od += P . FHt^T  (pure LDS + mma) ----
        {
            u32 ph[2][4], pl[2][4];
            const float* p0h = smf + PH_O + r0*20;
            const float* p0l = smf + PL_O + r0*20;
            #pragma unroll
            for (int kt = 0; kt < 2; kt++) {
                ph[kt][0] = FB(p0h[kt*8+tid]);     ph[kt][1] = FB(p0h[8*20 + kt*8+tid]);
                ph[kt][2] = FB(p0h[kt*8+tid+4]);   ph[kt][3] = FB(p0h[8*20 + kt*8+tid+4]);
                pl[kt][0] = FB(p0l[kt*8+tid]);     pl[kt][1] = FB(p0l[8*20 + kt*8+tid]);
                pl[kt][2] = FB(p0l[kt*8+tid+4]);   pl[kt][3] = FB(p0l[8*20 + kt*8+tid+4]);
            }
            #pragma unroll
            for (int nt = 0; nt < 16; nt++) {
                const float* fh = smf + FH_O + (128*half + nt*8 + gid)*20;
                const float* fl = smf + FL_O + (128*half + nt*8 + gid)*20;
                #pragma unroll
                for (int kt = 0; kt < 2; kt++) {
                    u32 bh[2], bl[2];
                    bh[0] = FB(fh[kt*8+tid]); bh[1] = FB(fh[kt*8+tid+4]);
                    bl[0] = FB(fl[kt*8+tid]); bl[1] = FB(fl[kt*8+tid+4]);
                    mma8(od[nt], ph[kt], bh);
                    mma8(od[nt], ph[kt], bl);
                    mma8(od[nt], pl[kt], bh);
                }
            }
        }
        __syncthreads();
        if (c < 63) {   // F(c+1) hi/lo (single buffer; PV(c) done)
            const float* Fhn = Fhg + (size_t)(c+1)*16;
            const float* Fln = Flg + (size_t)(c+1)*16;
            #pragma unroll
            for (int i = 0; i < 4; i++) { int id = i*256 + t, cc = id >> 2, mm = id & 3;
                cp16(sb + (u32)(FH_O + cc*20 + mm*4)*4, Fhn + (size_t)cc*1024 + mm*4);
                cp16(sb + (u32)(FL_O + cc*20 + mm*4)*4, Fln + (size_t)cc*1024 + mm*4); }
            cp_commit();
        }
    }

    // ---- epilogue ----
    float sc = scp[0];
    float inv0 = sc / smf[LA_O + r0];
    float inv1 = sc / smf[LA_O + r0 + 8];
    float* outB = out + (size_t)b*256*4096 + nblk*64;
    #pragma unroll
    for (int nt = 0; nt < 16; nt++) {
        int ch = 128*half + nt*8 + 2*tid;
        float* p0 = outB + (size_t)ch*4096;
        p0[r0]            = od[nt][0]*inv0;
        p0[4096 + r0]     = od[nt][1]*inv0;
        p0[r0 + 8]        = od[nt][2]*inv1;
        p0[4096 + r0 + 8] = od[nt][3]*inv1;
    }
}

extern "C" void kernel_launch(void* const* d_in, const int* in_sizes, int n_in,
                              void* d_out, int out_size)
{
    conv_k<<<dim3(8, 4, 8), 256>>>((const float*)d_in[1], (const float*)d_in[2],
        (const float*)d_in[3], (const float*)d_in[4],
        (const float*)d_in[5], (const float*)d_in[6]);
    transp_k<<<dim3(16, 4, 8), 256>>>();
    fc_k<false><<<256, 256>>>((const float*)d_in[0], (const float*)d_in[7],
                              (const float*)d_in[8]);
    fc_k<true ><<<64,  256>>>(nullptr, (const float*)d_in[9],
                              (const float*)d_in[10]);
    cudaFuncSetAttribute(attn_k, cudaFuncAttributeMaxDynamicSharedMemorySize, SMF*4);
    attn_k<<<dim3(64, 8), 256, SMF*4>>>((const float*)d_in[11], (float*)d_out);
}

// round 16
// speedup vs baseline: 1.2836x; 1.1240x over previous
#include <cuda_runtime.h>
#include <math.h>
#include <stdint.h>
typedef unsigned long long ull;
typedef unsigned int u32;

__device__ float g_FH  [8*1024*256];  // conv out [b][m][c]
__device__ float g_Ft_hi[8*256*1024]; // FHt hi [b][c][m]
__device__ float g_Ft_lo[8*256*1024];
__device__ float g_Q   [8*4096*64];
__device__ float g_K_hi[8*1024*64];
__device__ float g_K_lo[8*1024*64];

__device__ __forceinline__ void fma2(ull &d, ull a, ull b) {
    asm("fma.rn.f32x2 %0, %1, %2, %0;" : "+l"(d) : "l"(a), "l"(b));
}
__device__ __forceinline__ ull pk2(float x) {
    ull r; asm("mov.b64 %0, {%1, %1};" : "=l"(r) : "r"(__float_as_uint(x))); return r;
}
__device__ __forceinline__ float2 upk(ull v) {
    float2 f; asm("mov.b64 {%0, %1}, %2;" : "=f"(f.x), "=f"(f.y) : "l"(v)); return f;
}
__device__ __forceinline__ u32 cvta_s(const void* p) {
    return (u32)__cvta_generic_to_shared(p);
}
__device__ __forceinline__ void cp16(u32 dst, const void* src) {
    asm volatile("cp.async.cg.shared.global [%0], [%1], 16;\n" :: "r"(dst), "l"(src) : "memory");
}
__device__ __forceinline__ void cp_commit() {
    asm volatile("cp.async.commit_group;\n" ::: "memory");
}
template<int N> __device__ __forceinline__ void cp_wait() {
    asm volatile("cp.async.wait_group %0;\n" :: "n"(N) : "memory");
}
__device__ __forceinline__ u32 tf32c(float f) {
    u32 r; asm("cvt.rna.tf32.f32 %0, %1;" : "=r"(r) : "f"(f)); return r;
}
__device__ __forceinline__ void tsplit(float f, u32 &h, u32 &l) {
    h = tf32c(f); l = tf32c(f - __uint_as_float(h));
}
__device__ __forceinline__ void mma8(float* d, const u32* a, const u32* b) {
    asm volatile("mma.sync.aligned.m16n8k8.row.col.f32.tf32.tf32.f32 "
        "{%0,%1,%2,%3},{%4,%5,%6,%7},{%8,%9},{%0,%1,%2,%3};"
        : "+f"(d[0]), "+f"(d[1]), "+f"(d[2]), "+f"(d[3])
        : "r"(a[0]), "r"(a[1]), "r"(a[2]), "r"(a[3]), "r"(b[0]), "r"(b[1]));
}
#define FB(x) __float_as_uint(x)

// ======================= conv+BN+ReLU (proven) =============================
__global__ void __launch_bounds__(256) conv_k(
    const float* __restrict__ FHin, const float* __restrict__ Wc,
    const float* __restrict__ gam, const float* __restrict__ bet,
    const float* __restrict__ mu,  const float* __restrict__ var)
{
    __shared__ float Ws[64*64];
    __shared__ float Xs[64*128];
    const int t = threadIdx.x, tx = t & 31, ty = t >> 5;
    const int st = blockIdx.x, ot = blockIdx.y, b = blockIdx.z;
    const float* Xg = FHin + (size_t)b*512*1024 + st*128;
    const float* Wg = Wc + (size_t)ot*64*512;
    ull acc[8][2];
    #pragma unroll
    for (int r = 0; r < 8; r++) { acc[r][0] = 0ull; acc[r][1] = 0ull; }
    for (int kc = 0; kc < 8; kc++) {
        __syncthreads();
        #pragma unroll
        for (int i = 0; i < 16; i++) {
            int id = i*256 + t; int row = id >> 6, col = id & 63;
            Ws[row*64 + col] = Wg[(size_t)row*512 + kc*64 + col];
        }
        #pragma unroll
        for (int i = 0; i < 8; i++) {
            int id = i*256 + t; int row = id >> 5, c4 = id & 31;
            *(float4*)&Xs[row*128 + c4*4] =
                *(const float4*)(Xg + (size_t)(kc*64 + row)*1024 + c4*4);
        }
        __syncthreads();
        #pragma unroll 8
        for (int k = 0; k < 64; k++) {
            ull x0 = *(const ull*)&Xs[k*128 + tx*4];
            ull x1 = *(const ull*)&Xs[k*128 + tx*4 + 2];
            #pragma unroll
            for (int r = 0; r < 8; r++) {
                ull wv = pk2(Ws[(ty*8 + r)*64 + k]);
                fma2(acc[r][0], wv, x0);
                fma2(acc[r][1], wv, x1);
            }
        }
    }
    #pragma unroll
    for (int r = 0; r < 8; r++) {
        int o = ot*64 + ty*8 + r;
        float inv = gam[o] * rsqrtf(var[o] + 1e-5f);
        float bs  = bet[o] - mu[o]*inv;
        float2 a = upk(acc[r][0]), c2 = upk(acc[r][1]);
        float4 v;
        v.x = fmaxf(fmaf(a.x,  inv, bs), 0.f);
        v.y = fmaxf(fmaf(a.y,  inv, bs), 0.f);
        v.z = fmaxf(fmaf(c2.x, inv, bs), 0.f);
        v.w = fmaxf(fmaf(c2.y, inv, bs), 0.f);
        *(float4*)&g_FH[((size_t)b*256 + o)*1024 + st*128 + tx*4] = v;
    }
}

// ====== transpose + tf32-split: g_FH [b][m][c] -> g_Ft_hi/lo [b][c][m] =====
__global__ void __launch_bounds__(256) transp_k()
{
    __shared__ float ts[64*65];
    const int t = threadIdx.x;
    const int i0 = blockIdx.x*64, j0 = blockIdx.y*64, b = blockIdx.z;
    const float* src = g_FH + (size_t)b*1024*256;
    float* dh = g_Ft_hi + (size_t)b*256*1024;
    float* dl = g_Ft_lo + (size_t)b*256*1024;
    const int r = t >> 4, c4 = (t & 15)*4;
    #pragma unroll
    for (int k2 = 0; k2 < 4; k2++) {
        int il = r + k2*16;
        float4 v = *(const float4*)(src + (size_t)(i0+il)*256 + j0 + c4);
        ts[il*65 + c4+0] = v.x; ts[il*65 + c4+1] = v.y;
        ts[il*65 + c4+2] = v.z; ts[il*65 + c4+3] = v.w;
    }
    __syncthreads();
    #pragma unroll
    for (int k2 = 0; k2 < 4; k2++) {
        int jr = r + k2*16;
        float4 v;
        v.x = ts[(c4+0)*65 + jr]; v.y = ts[(c4+1)*65 + jr];
        v.z = ts[(c4+2)*65 + jr]; v.w = ts[(c4+3)*65 + jr];
        float4 vh, vl; u32 h, lo;
        tsplit(v.x, h, lo); vh.x = __uint_as_float(h); vl.x = __uint_as_float(lo);
        tsplit(v.y, h, lo); vh.y = __uint_as_float(h); vl.y = __uint_as_float(lo);
        tsplit(v.z, h, lo); vh.z = __uint_as_float(h); vl.z = __uint_as_float(lo);
        tsplit(v.w, h, lo); vh.w = __uint_as_float(h); vl.w = __uint_as_float(lo);
        *(float4*)(dh + (size_t)(j0+jr)*1024 + i0 + c4) = vh;
        *(float4*)(dl + (size_t)(j0+jr)*1024 + i0 + c4) = vl;
    }
}

// ====== fc GEMM (proven core); Q raw, K split hi/lo =========================
template<bool TO_K>
__global__ void __launch_bounds__(256) fc_k(
    const float* __restrict__ Xin, const float* __restrict__ W,
    const float* __restrict__ bias)
{
    __shared__ float Xs[128*64];
    __shared__ float Ws[64*66];
    const int t = threadIdx.x, tx = t & 15, ty = t >> 4;
    const int n0 = blockIdx.x*128;
    const float* X = TO_K ? (const float*)g_FH : Xin;
    ull acc[8][2];
    #pragma unroll
    for (int r = 0; r < 8; r++) { acc[r][0] = 0ull; acc[r][1] = 0ull; }
    for (int kc = 0; kc < 4; kc++) {
        __syncthreads();
        #pragma unroll
        for (int i = 0; i < 8; i++) {
            int id = i*256 + t; int row = id >> 4, c4 = id & 15;
            *(float4*)&Xs[row*64 + c4*4] =
                *(const float4*)(X + (size_t)(n0+row)*256 + kc*64 + c4*4);
        }
        #pragma unroll
        for (int i = 0; i < 16; i++) {
            int id = i*256 + t; int d = id >> 6, c = id & 63;
            Ws[c*66 + d] = W[(size_t)d*256 + kc*64 + c];
        }
        __syncthreads();
        #pragma unroll 8
        for (int c = 0; c < 64; c++) {
            ull w0 = *(const ull*)&Ws[c*66 + tx*4];
            ull w1 = *(const ull*)&Ws[c*66 + tx*4 + 2];
            #pragma unroll
            for (int r = 0; r < 8; r++) {
                ull xv = pk2(Xs[(ty*8 + r)*64 + c]);
                fma2(acc[r][0], xv, w0);
                fma2(acc[r][1], xv, w1);
            }
        }
    }
    float4 bv = *(const float4*)(bias + tx*4);
    #pragma unroll
    for (int r = 0; r < 8; r++) {
        float2 a = upk(acc[r][0]), c2 = upk(acc[r][1]);
        float4 v = make_float4(a.x + bv.x, a.y + bv.y, c2.x + bv.z, c2.y + bv.w);
        size_t idx = (size_t)(n0 + ty*8 + r)*64 + tx*4;
        if (!TO_K) {
            *(float4*)&g_Q[idx] = v;
        } else {
            float4 vh, vl; u32 h, lo;
            tsplit(v.x, h, lo); vh.x = __uint_as_float(h); vl.x = __uint_as_float(lo);
            tsplit(v.y, h, lo); vh.y = __uint_as_float(h); vl.y = __uint_as_float(lo);
            tsplit(v.z, h, lo); vh.z = __uint_as_float(h); vl.z = __uint_as_float(lo);
            tsplit(v.w, h, lo); vh.w = __uint_as_float(h); vl.w = __uint_as_float(lo);
            *(float4*)&g_K_hi[idx] = vh;
            *(float4*)&g_K_lo[idx] = vl;
        }
    }
}

// == attention: S 3xTF32, PV 2xTF32 (P unsplit tf32), mma.sync ==============
// 256 thr / 8 warps; 64 rows x 256 cols; 64 m-chunks of 16.
#define QH_O 0        // [64][68]
#define QL_O 4352
#define KH_O 8704     // 2 x [16][68]
#define KL_O 10880
#define FH_O 13056    // [256][20]
#define FL_O 18176
#define PH_O 23296    // [64][20]  (tf32-rounded P, no lo part)
#define PS_O 24576    // [2][64]
#define LA_O 24704    // [64]
#define SMF  24768

__global__ void __launch_bounds__(256, 2) attn_k(
    const float* __restrict__ scp, float* __restrict__ out)
{
    extern __shared__ float smf[];
    const u32 sb = cvta_s(smf);
    const int b = blockIdx.y, nblk = blockIdx.x;
    const int t = threadIdx.x, w = t >> 5, l = t & 31;
    const int gid = l >> 2, tid = l & 3;
    const int band = w & 3, half = w >> 2;
    const int r0 = 16*band + gid;

    const float* Qg  = g_Q    + ((size_t)b*4096 + nblk*64)*64;
    const float* Khg = g_K_hi + (size_t)b*1024*64;
    const float* Klg = g_K_lo + (size_t)b*1024*64;
    const float* Fhg = g_Ft_hi + (size_t)b*256*1024;
    const float* Flg = g_Ft_lo + (size_t)b*256*1024;

    // prologue: G1{Q raw, K0 hi/lo}, G2{F0 hi/lo}
    #pragma unroll
    for (int i = 0; i < 4; i++) { int id = i*256 + t, r = id >> 4, q = id & 15;
        cp16(sb + (u32)(QH_O + r*68 + q*4)*4, Qg + (size_t)r*64 + q*4); }
    { int r = t >> 4, q = t & 15;
      cp16(sb + (u32)(KH_O + r*68 + q*4)*4, Khg + (size_t)r*64 + q*4);
      cp16(sb + (u32)(KL_O + r*68 + q*4)*4, Klg + (size_t)r*64 + q*4); }
    cp_commit();
    #pragma unroll
    for (int i = 0; i < 4; i++) { int id = i*256 + t, cc = id >> 2, mm = id & 3;
        cp16(sb + (u32)(FH_O + cc*20 + mm*4)*4, Fhg + (size_t)cc*1024 + mm*4);
        cp16(sb + (u32)(FL_O + cc*20 + mm*4)*4, Flg + (size_t)cc*1024 + mm*4); }
    cp_commit();
    cp_wait<1>();
    __syncthreads();
    // split Q in place: QH -> hi, QL -> lo
    #pragma unroll
    for (int i = 0; i < 16; i++) {
        int id = i*256 + t, r = id >> 6, col = id & 63;
        float f = smf[QH_O + r*68 + col];
        u32 h, lo; tsplit(f, h, lo);
        smf[QH_O + r*68 + col] = __uint_as_float(h);
        smf[QL_O + r*68 + col] = __uint_as_float(lo);
    }
    if (t < 64) smf[LA_O + t] = 0.f;
    __syncthreads();

    float od[16][4];
    #pragma unroll
    for (int i = 0; i < 16; i++) { od[i][0]=0.f; od[i][1]=0.f; od[i][2]=0.f; od[i][3]=0.f; }

    for (int c = 0; c < 64; c++) {
        cp_wait<1>();
        __syncthreads();

        // ---- S: one 16x8 tile per warp (3xTF32) ----
        float sd[4] = {0.f, 0.f, 0.f, 0.f};
        {
            const float* qh  = smf + QH_O + r0*68;
            const float* ql  = smf + QL_O + r0*68;
            const float* kh  = smf + KH_O + (c & 1)*1088 + (8*half + gid)*68;
            const float* kl  = smf + KL_O + (c & 1)*1088 + (8*half + gid)*68;
            #pragma unroll
            for (int kt = 0; kt < 8; kt++) {
                u32 ah[4], al[4], bh[2], bl[2];
                ah[0] = FB(qh[kt*8+tid]);       ah[1] = FB(qh[8*68 + kt*8+tid]);
                ah[2] = FB(qh[kt*8+tid+4]);     ah[3] = FB(qh[8*68 + kt*8+tid+4]);
                al[0] = FB(ql[kt*8+tid]);       al[1] = FB(ql[8*68 + kt*8+tid]);
                al[2] = FB(ql[kt*8+tid+4]);     al[3] = FB(ql[8*68 + kt*8+tid+4]);
                bh[0] = FB(kh[kt*8+tid]);       bh[1] = FB(kh[kt*8+tid+4]);
                bl[0] = FB(kl[kt*8+tid]);       bl[1] = FB(kl[kt*8+tid+4]);
                mma8(sd, ah, bh);
                mma8(sd, ah, bl);
                mma8(sd, al, bh);
            }
        }
        if (c < 63) {   // prefetch K(c+1) hi/lo
            const float* Khn = Khg + (size_t)(c+1)*16*64;
            const float* Kln = Klg + (size_t)(c+1)*16*64;
            int r = t >> 4, q = t & 15;
            u32 kb = (u32)(KH_O + ((c+1) & 1)*1088 + r*68 + q*4)*4;
            u32 lb = (u32)(KL_O + ((c+1) & 1)*1088 + r*68 + q*4)*4;
            cp16(sb + kb, Khn + (size_t)r*64 + q*4);
            cp16(sb + lb, Kln + (size_t)r*64 + q*4);
            cp_commit();
        }

        // ---- softmax (naive; safe since |S| <~ 45); P stored tf32-rounded ----
        {
            float e0 = __expf(sd[0]), e1 = __expf(sd[1]);
            float e2 = __expf(sd[2]), e3 = __expf(sd[3]);
            float l0 = e0 + e1, l1 = e2 + e3;
            l0 += __shfl_xor_sync(~0u, l0, 1); l0 += __shfl_xor_sync(~0u, l0, 2);
            l1 += __shfl_xor_sync(~0u, l1, 1); l1 += __shfl_xor_sync(~0u, l1, 2);
            if (tid == 0) {
                smf[PS_O + half*64 + r0]     = l0;
                smf[PS_O + half*64 + r0 + 8] = l1;
            }
            int mc = 8*half + 2*tid;
            *(float2*)&smf[PH_O + r0*20 + mc] =
                make_float2(__uint_as_float(tf32c(e0)), __uint_as_float(tf32c(e1)));
            *(float2*)&smf[PH_O + (r0+8)*20 + mc] =
                make_float2(__uint_as_float(tf32c(e2)), __uint_as_float(tf32c(e3)));
        }
        if (c < 63) cp_wait<1>(); else cp_wait<0>();
        __syncthreads();
        if (t < 64) smf[LA_O + t] += smf[PS_O + t] + smf[PS_O + 64 + t];

        // ---- PV: od += P . FHt^T  (2xTF32: P*Fhi + P*Flo) ----
        {
            u32 ph[2][4];
            const float* p0h = smf + PH_O + r0*20;
            #pragma unroll
            for (int kt = 0; kt < 2; kt++) {
                ph[kt][0] = FB(p0h[kt*8+tid]);     ph[kt][1] = FB(p0h[8*20 + kt*8+tid]);
                ph[kt][2] = FB(p0h[kt*8+tid+4]);   ph[kt][3] = FB(p0h[8*20 + kt*8+tid+4]);
            }
            #pragma unroll
            for (int nt = 0; nt < 16; nt++) {
                const float* fh = smf + FH_O + (128*half + nt*8 + gid)*20;
                const float* fl = smf + FL_O + (128*half + nt*8 + gid)*20;
                #pragma unroll
                for (int kt = 0; kt < 2; kt++) {
                    u32 bh[2], bl[2];
                    bh[0] = FB(fh[kt*8+tid]); bh[1] = FB(fh[kt*8+tid+4]);
                    bl[0] = FB(fl[kt*8+tid]); bl[1] = FB(fl[kt*8+tid+4]);
                    mma8(od[nt], ph[kt], bh);
                    mma8(od[nt], ph[kt], bl);
                }
            }
        }
        __syncthreads();
        if (c < 63) {   // F(c+1) hi/lo (single buffer; PV(c) done)
            const float* Fhn = Fhg + (size_t)(c+1)*16;
            const float* Fln = Flg + (size_t)(c+1)*16;
            #pragma unroll
            for (int i = 0; i < 4; i++) { int id = i*256 + t, cc = id >> 2, mm = id & 3;
                cp16(sb + (u32)(FH_O + cc*20 + mm*4)*4, Fhn + (size_t)cc*1024 + mm*4);
                cp16(sb + (u32)(FL_O + cc*20 + mm*4)*4, Fln + (size_t)cc*1024 + mm*4); }
            cp_commit();
        }
    }

    // ---- epilogue ----
    float sc = scp[0];
    float inv0 = sc / smf[LA_O + r0];
    float inv1 = sc / smf[LA_O + r0 + 8];
    float* outB = out + (size_t)b*256*4096 + nblk*64;
    #pragma unroll
    for (int nt = 0; nt < 16; nt++) {
        int ch = 128*half + nt*8 + 2*tid;
        float* p0 = outB + (size_t)ch*4096;
        p0[r0]            = od[nt][0]*inv0;
        p0[4096 + r0]     = od[nt][1]*inv0;
        p0[r0 + 8]        = od[nt][2]*inv1;
        p0[4096 + r0 + 8] = od[nt][3]*inv1;
    }
}

extern "C" void kernel_launch(void* const* d_in, const int* in_sizes, int n_in,
                              void* d_out, int out_size)
{
    conv_k<<<dim3(8, 4, 8), 256>>>((const float*)d_in[1], (const float*)d_in[2],
        (const float*)d_in[3], (const float*)d_in[4],
        (const float*)d_in[5], (const float*)d_in[6]);
    transp_k<<<dim3(16, 4, 8), 256>>>();
    fc_k<false><<<256, 256>>>((const float*)d_in[0], (const float*)d_in[7],
                              (const float*)d_in[8]);
    fc_k<true ><<<64,  256>>>(nullptr, (const float*)d_in[9],
                              (const float*)d_in[10]);
    cudaFuncSetAttribute(attn_k, cudaFuncAttributeMaxDynamicSharedMemorySize, SMF*4);
    attn_k<<<dim3(64, 8), 256, SMF*4>>>((const float*)d_in[11], (float*)d_out);
}

// round 17
// speedup vs baseline: 1.6818x; 1.3102x over previous
#include <cuda_runtime.h>
#include <math.h>
#include <stdint.h>
typedef unsigned long long ull;
typedef unsigned int u32;

__device__ float g_FH  [8*1024*256];  // conv out [b][m][c]
__device__ float g_Ft  [8*256*1024];  // FHt tf32-rounded [b][c][m]
__device__ float g_Q   [8*4096*64];
__device__ float g_K_hi[8*1024*64];
__device__ float g_K_lo[8*1024*64];

__device__ __forceinline__ void fma2(ull &d, ull a, ull b) {
    asm("fma.rn.f32x2 %0, %1, %2, %0;" : "+l"(d) : "l"(a), "l"(b));
}
__device__ __forceinline__ ull pk2(float x) {
    ull r; asm("mov.b64 %0, {%1, %1};" : "=l"(r) : "r"(__float_as_uint(x))); return r;
}
__device__ __forceinline__ float2 upk(ull v) {
    float2 f; asm("mov.b64 {%0, %1}, %2;" : "=f"(f.x), "=f"(f.y) : "l"(v)); return f;
}
__device__ __forceinline__ u32 cvta_s(const void* p) {
    return (u32)__cvta_generic_to_shared(p);
}
__device__ __forceinline__ void cp16(u32 dst, const void* src) {
    asm volatile("cp.async.cg.shared.global [%0], [%1], 16;\n" :: "r"(dst), "l"(src) : "memory");
}
__device__ __forceinline__ void cp_commit() {
    asm volatile("cp.async.commit_group;\n" ::: "memory");
}
template<int N> __device__ __forceinline__ void cp_wait() {
    asm volatile("cp.async.wait_group %0;\n" :: "n"(N) : "memory");
}
__device__ __forceinline__ u32 tf32c(float f) {
    u32 r; asm("cvt.rna.tf32.f32 %0, %1;" : "=r"(r) : "f"(f)); return r;
}
__device__ __forceinline__ void tsplit(float f, u32 &h, u32 &l) {
    h = tf32c(f); l = tf32c(f - __uint_as_float(h));
}
__device__ __forceinline__ void mma8(float* d, const u32* a, const u32* b) {
    asm volatile("mma.sync.aligned.m16n8k8.row.col.f32.tf32.tf32.f32 "
        "{%0,%1,%2,%3},{%4,%5,%6,%7},{%8,%9},{%0,%1,%2,%3};"
        : "+f"(d[0]), "+f"(d[1]), "+f"(d[2]), "+f"(d[3])
        : "r"(a[0]), "r"(a[1]), "r"(a[2]), "r"(a[3]), "r"(b[0]), "r"(b[1]));
}
#define FB(x) __float_as_uint(x)

// ======================= conv+BN+ReLU (proven) =============================
__global__ void __launch_bounds__(256) conv_k(
    const float* __restrict__ FHin, const float* __restrict__ Wc,
    const float* __restrict__ gam, const float* __restrict__ bet,
    const float* __restrict__ mu,  const float* __restrict__ var)
{
    __shared__ float Ws[64*64];
    __shared__ float Xs[64*128];
    const int t = threadIdx.x, tx = t & 31, ty = t >> 5;
    const int st = blockIdx.x, ot = blockIdx.y, b = blockIdx.z;
    const float* Xg = FHin + (size_t)b*512*1024 + st*128;
    const float* Wg = Wc + (size_t)ot*64*512;
    ull acc[8][2];
    #pragma unroll
    for (int r = 0; r < 8; r++) { acc[r][0] = 0ull; acc[r][1] = 0ull; }
    for (int kc = 0; kc < 8; kc++) {
        __syncthreads();
        #pragma unroll
        for (int i = 0; i < 16; i++) {
            int id = i*256 + t; int row = id >> 6, col = id & 63;
            Ws[row*64 + col] = Wg[(size_t)row*512 + kc*64 + col];
        }
        #pragma unroll
        for (int i = 0; i < 8; i++) {
            int id = i*256 + t; int row = id >> 5, c4 = id & 31;
            *(float4*)&Xs[row*128 + c4*4] =
                *(const float4*)(Xg + (size_t)(kc*64 + row)*1024 + c4*4);
        }
        __syncthreads();
        #pragma unroll 8
        for (int k = 0; k < 64; k++) {
            ull x0 = *(const ull*)&Xs[k*128 + tx*4];
            ull x1 = *(const ull*)&Xs[k*128 + tx*4 + 2];
            #pragma unroll
            for (int r = 0; r < 8; r++) {
                ull wv = pk2(Ws[(ty*8 + r)*64 + k]);
                fma2(acc[r][0], wv, x0);
                fma2(acc[r][1], wv, x1);
            }
        }
    }
    #pragma unroll
    for (int r = 0; r < 8; r++) {
        int o = ot*64 + ty*8 + r;
        float inv = gam[o] * rsqrtf(var[o] + 1e-5f);
        float bs  = bet[o] - mu[o]*inv;
        float2 a = upk(acc[r][0]), c2 = upk(acc[r][1]);
        float4 v;
        v.x = fmaxf(fmaf(a.x,  inv, bs), 0.f);
        v.y = fmaxf(fmaf(a.y,  inv, bs), 0.f);
        v.z = fmaxf(fmaf(c2.x, inv, bs), 0.f);
        v.w = fmaxf(fmaf(c2.y, inv, bs), 0.f);
        *(float4*)&g_FH[((size_t)b*256 + o)*1024 + st*128 + tx*4] = v;
    }
}

// == transpose + tf32-round: g_FH [b][m][c] -> g_Ft [b][c][m] (single) ======
__global__ void __launch_bounds__(256) transp_k()
{
    __shared__ float ts[64*65];
    const int t = threadIdx.x;
    const int i0 = blockIdx.x*64, j0 = blockIdx.y*64, b = blockIdx.z;
    const float* src = g_FH + (size_t)b*1024*256;
    float* dh = g_Ft + (size_t)b*256*1024;
    const int r = t >> 4, c4 = (t & 15)*4;
    #pragma unroll
    for (int k2 = 0; k2 < 4; k2++) {
        int il = r + k2*16;
        float4 v = *(const float4*)(src + (size_t)(i0+il)*256 + j0 + c4);
        ts[il*65 + c4+0] = v.x; ts[il*65 + c4+1] = v.y;
        ts[il*65 + c4+2] = v.z; ts[il*65 + c4+3] = v.w;
    }
    __syncthreads();
    #pragma unroll
    for (int k2 = 0; k2 < 4; k2++) {
        int jr = r + k2*16;
        float4 vh;
        vh.x = __uint_as_float(tf32c(ts[(c4+0)*65 + jr]));
        vh.y = __uint_as_float(tf32c(ts[(c4+1)*65 + jr]));
        vh.z = __uint_as_float(tf32c(ts[(c4+2)*65 + jr]));
        vh.w = __uint_as_float(tf32c(ts[(c4+3)*65 + jr]));
        *(float4*)(dh + (size_t)(j0+jr)*1024 + i0 + c4) = vh;
    }
}

// ====== fc GEMM (proven core); Q raw, K split hi/lo =========================
template<bool TO_K>
__global__ void __launch_bounds__(256) fc_k(
    const float* __restrict__ Xin, const float* __restrict__ W,
    const float* __restrict__ bias)
{
    __shared__ float Xs[128*64];
    __shared__ float Ws[64*66];
    const int t = threadIdx.x, tx = t & 15, ty = t >> 4;
    const int n0 = blockIdx.x*128;
    const float* X = TO_K ? (const float*)g_FH : Xin;
    ull acc[8][2];
    #pragma unroll
    for (int r = 0; r < 8; r++) { acc[r][0] = 0ull; acc[r][1] = 0ull; }
    for (int kc = 0; kc < 4; kc++) {
        __syncthreads();
        #pragma unroll
        for (int i = 0; i < 8; i++) {
            int id = i*256 + t; int row = id >> 4, c4 = id & 15;
            *(float4*)&Xs[row*64 + c4*4] =
                *(const float4*)(X + (size_t)(n0+row)*256 + kc*64 + c4*4);
        }
        #pragma unroll
        for (int i = 0; i < 16; i++) {
            int id = i*256 + t; int d = id >> 6, c = id & 63;
            Ws[c*66 + d] = W[(size_t)d*256 + kc*64 + c];
        }
        __syncthreads();
        #pragma unroll 8
        for (int c = 0; c < 64; c++) {
            ull w0 = *(const ull*)&Ws[c*66 + tx*4];
            ull w1 = *(const ull*)&Ws[c*66 + tx*4 + 2];
            #pragma unroll
            for (int r = 0; r < 8; r++) {
                ull xv = pk2(Xs[(ty*8 + r)*64 + c]);
                fma2(acc[r][0], xv, w0);
                fma2(acc[r][1], xv, w1);
            }
        }
    }
    float4 bv = *(const float4*)(bias + tx*4);
    #pragma unroll
    for (int r = 0; r < 8; r++) {
        float2 a = upk(acc[r][0]), c2 = upk(acc[r][1]);
        float4 v = make_float4(a.x + bv.x, a.y + bv.y, c2.x + bv.z, c2.y + bv.w);
        size_t idx = (size_t)(n0 + ty*8 + r)*64 + tx*4;
        if (!TO_K) {
            *(float4*)&g_Q[idx] = v;
        } else {
            float4 vh, vl; u32 h, lo;
            tsplit(v.x, h, lo); vh.x = __uint_as_float(h); vl.x = __uint_as_float(lo);
            tsplit(v.y, h, lo); vh.y = __uint_as_float(h); vl.y = __uint_as_float(lo);
            tsplit(v.z, h, lo); vh.z = __uint_as_float(h); vl.z = __uint_as_float(lo);
            tsplit(v.w, h, lo); vh.w = __uint_as_float(h); vl.w = __uint_as_float(lo);
            *(float4*)&g_K_hi[idx] = vh;
            *(float4*)&g_K_lo[idx] = vl;
        }
    }
}

// == attention: S 3xTF32, PV 1xTF32 (P tf32, F tf32), mma.sync ==============
// 256 thr / 8 warps; 64 rows x 256 cols; 64 m-chunks of 16.
#define QH_O 0        // [64][68]
#define QL_O 4352
#define KH_O 8704     // 2 x [16][68]
#define KL_O 10880
#define FH_O 13056    // [256][20]
#define PH_O 18176    // [64][20]
#define PS_O 19456    // [2][64]
#define LA_O 19584    // [64]
#define SMF  19648

__global__ void __launch_bounds__(256, 2) attn_k(
    const float* __restrict__ scp, float* __restrict__ out)
{
    extern __shared__ float smf[];
    const u32 sb = cvta_s(smf);
    const int b = blockIdx.y, nblk = blockIdx.x;
    const int t = threadIdx.x, w = t >> 5, l = t & 31;
    const int gid = l >> 2, tid = l & 3;
    const int band = w & 3, half = w >> 2;
    const int r0 = 16*band + gid;

    const float* Qg  = g_Q    + ((size_t)b*4096 + nblk*64)*64;
    const float* Khg = g_K_hi + (size_t)b*1024*64;
    const float* Klg = g_K_lo + (size_t)b*1024*64;
    const float* Fhg = g_Ft   + (size_t)b*256*1024;

    // prologue: G1{Q raw, K0 hi/lo}, G2{F0}
    #pragma unroll
    for (int i = 0; i < 4; i++) { int id = i*256 + t, r = id >> 4, q = id & 15;
        cp16(sb + (u32)(QH_O + r*68 + q*4)*4, Qg + (size_t)r*64 + q*4); }
    { int r = t >> 4, q = t & 15;
      cp16(sb + (u32)(KH_O + r*68 + q*4)*4, Khg + (size_t)r*64 + q*4);
      cp16(sb + (u32)(KL_O + r*68 + q*4)*4, Klg + (size_t)r*64 + q*4); }
    cp_commit();
    #pragma unroll
    for (int i = 0; i < 4; i++) { int id = i*256 + t, cc = id >> 2, mm = id & 3;
        cp16(sb + (u32)(FH_O + cc*20 + mm*4)*4, Fhg + (size_t)cc*1024 + mm*4); }
    cp_commit();
    cp_wait<1>();
    __syncthreads();
    // split Q in place: QH -> hi, QL -> lo
    #pragma unroll
    for (int i = 0; i < 16; i++) {
        int id = i*256 + t, r = id >> 6, col = id & 63;
        float f = smf[QH_O + r*68 + col];
        u32 h, lo; tsplit(f, h, lo);
        smf[QH_O + r*68 + col] = __uint_as_float(h);
        smf[QL_O + r*68 + col] = __uint_as_float(lo);
    }
    if (t < 64) smf[LA_O + t] = 0.f;
    __syncthreads();

    float od[16][4];
    #pragma unroll
    for (int i = 0; i < 16; i++) { od[i][0]=0.f; od[i][1]=0.f; od[i][2]=0.f; od[i][3]=0.f; }

    for (int c = 0; c < 64; c++) {
        cp_wait<1>();
        __syncthreads();

        // ---- S: one 16x8 tile per warp (3xTF32) ----
        float sd[4] = {0.f, 0.f, 0.f, 0.f};
        {
            const float* qh  = smf + QH_O + r0*68;
            const float* ql  = smf + QL_O + r0*68;
            const float* kh  = smf + KH_O + (c & 1)*1088 + (8*half + gid)*68;
            const float* kl  = smf + KL_O + (c & 1)*1088 + (8*half + gid)*68;
            #pragma unroll
            for (int kt = 0; kt < 8; kt++) {
                u32 ah[4], al[4], bh[2], bl[2];
                ah[0] = FB(qh[kt*8+tid]);       ah[1] = FB(qh[8*68 + kt*8+tid]);
                ah[2] = FB(qh[kt*8+tid+4]);     ah[3] = FB(qh[8*68 + kt*8+tid+4]);
                al[0] = FB(ql[kt*8+tid]);       al[1] = FB(ql[8*68 + kt*8+tid]);
                al[2] = FB(ql[kt*8+tid+4]);     al[3] = FB(ql[8*68 + kt*8+tid+4]);
                bh[0] = FB(kh[kt*8+tid]);       bh[1] = FB(kh[kt*8+tid+4]);
                bl[0] = FB(kl[kt*8+tid]);       bl[1] = FB(kl[kt*8+tid+4]);
                mma8(sd, ah, bh);
                mma8(sd, ah, bl);
                mma8(sd, al, bh);
            }
        }
        if (c < 63) {   // prefetch K(c+1) hi/lo
            const float* Khn = Khg + (size_t)(c+1)*16*64;
            const float* Kln = Klg + (size_t)(c+1)*16*64;
            int r = t >> 4, q = t & 15;
            u32 kb = (u32)(KH_O + ((c+1) & 1)*1088 + r*68 + q*4)*4;
            u32 lb = (u32)(KL_O + ((c+1) & 1)*1088 + r*68 + q*4)*4;
            cp16(sb + kb, Khn + (size_t)r*64 + q*4);
            cp16(sb + lb, Kln + (size_t)r*64 + q*4);
            cp_commit();
        }

        // ---- softmax (naive; safe since |S| <~ 45); P stored tf32-rounded ----
        {
            float e0 = __expf(sd[0]), e1 = __expf(sd[1]);
            float e2 = __expf(sd[2]), e3 = __expf(sd[3]);
            float l0 = e0 + e1, l1 = e2 + e3;
            l0 += __shfl_xor_sync(~0u, l0, 1); l0 += __shfl_xor_sync(~0u, l0, 2);
            l1 += __shfl_xor_sync(~0u, l1, 1); l1 += __shfl_xor_sync(~0u, l1, 2);
            if (tid == 0) {
                smf[PS_O + half*64 + r0]     = l0;
                smf[PS_O + half*64 + r0 + 8] = l1;
            }
            int mc = 8*half + 2*tid;
            *(float2*)&smf[PH_O + r0*20 + mc] =
                make_float2(__uint_as_float(tf32c(e0)), __uint_as_float(tf32c(e1)));
            *(float2*)&smf[PH_O + (r0+8)*20 + mc] =
                make_float2(__uint_as_float(tf32c(e2)), __uint_as_float(tf32c(e3)));
        }
        if (c < 63) cp_wait<1>(); else cp_wait<0>();
        __syncthreads();
        if (t < 64) smf[LA_O + t] += smf[PS_O + t] + smf[PS_O + 64 + t];

        // ---- PV: od += P . F^T  (single tf32 mma per tile) ----
        {
            u32 ph[2][4];
            const float* p0h = smf + PH_O + r0*20;
            #pragma unroll
            for (int kt = 0; kt < 2; kt++) {
                ph[kt][0] = FB(p0h[kt*8+tid]);     ph[kt][1] = FB(p0h[8*20 + kt*8+tid]);
                ph[kt][2] = FB(p0h[kt*8+tid+4]);   ph[kt][3] = FB(p0h[8*20 + kt*8+tid+4]);
            }
            #pragma unroll
            for (int nt = 0; nt < 16; nt++) {
                const float* fh = smf + FH_O + (128*half + nt*8 + gid)*20;
                #pragma unroll
                for (int kt = 0; kt < 2; kt++) {
                    u32 bh[2];
                    bh[0] = FB(fh[kt*8+tid]); bh[1] = FB(fh[kt*8+tid+4]);
                    mma8(od[nt], ph[kt], bh);
                }
            }
        }
        __syncthreads();
        if (c < 63) {   // F(c+1) (single buffer; PV(c) done)
            const float* Fhn = Fhg + (size_t)(c+1)*16;
            #pragma unroll
            for (int i = 0; i < 4; i++) { int id = i*256 + t, cc = id >> 2, mm = id & 3;
                cp16(sb + (u32)(FH_O + cc*20 + mm*4)*4, Fhn + (size_t)cc*1024 + mm*4); }
            cp_commit();
        }
    }

    // ---- epilogue ----
    float sc = scp[0];
    float inv0 = sc / smf[LA_O + r0];
    float inv1 = sc / smf[LA_O + r0 + 8];
    float* outB = out + (size_t)b*256*4096 + nblk*64;
    #pragma unroll
    for (int nt = 0; nt < 16; nt++) {
        int ch = 128*half + nt*8 + 2*tid;
        float* p0 = outB + (size_t)ch*4096;
        p0[r0]            = od[nt][0]*inv0;
        p0[4096 + r0]     = od[nt][1]*inv0;
        p0[r0 + 8]        = od[nt][2]*inv1;
        p0[4096 + r0 + 8] = od[nt][3]*inv1;
    }
}

extern "C" void kernel_launch(void* const* d_in, const int* in_sizes, int n_in,
                              void* d_out, int out_size)
{
    conv_k<<<dim3(8, 4, 8), 256>>>((const float*)d_in[1], (const float*)d_in[2],
        (const float*)d_in[3], (const float*)d_in[4],
        (const float*)d_in[5], (const float*)d_in[6]);
    transp_k<<<dim3(16, 4, 8), 256>>>();
    fc_k<false><<<256, 256>>>((const float*)d_in[0], (const float*)d_in[7],
                              (const float*)d_in[8]);
    fc_k<true ><<<64,  256>>>(nullptr, (const float*)d_in[9],
                              (const float*)d_in[10]);
    cudaFuncSetAttribute(attn_k, cudaFuncAttributeMaxDynamicSharedMemorySize, SMF*4);
    attn_k<<<dim3(64, 8), 256, SMF*4>>>((const float*)d_in[11], (float*)d_out);
}